// round 16
// baseline (speedup 1.0000x reference)
#include <cuda_runtime.h>
#include <cuda_fp16.h>
#include <cstdint>

// ---------------------------------------------------------------------------
// Problem constants
// ---------------------------------------------------------------------------
#define BATCH   32768
#define IMG     28
#define KPIX    784      // GEMM K
#define OUT_HW  26
#define OPIX    676
#define HID     200
#define HPAD    256      // padded hidden (GEMM N)
#define NOUT    10

#define BM      128      // M rows per CTA
#define BK      64       // K per chunk (fp16 -> 128B rows, SW128)
#define NCHUNK  13       // 12*64 + 16
#define NSTAGE  4        // ring depth
#define GEMM_THREADS 256
#define NTEAM   96       // loader threads per team (3 warps)
#define NUNIT   1024     // 8-float units per chunk (128 rows x 8)
#define LPU     11       // units per team thread (96*11 >= 1024)

// idesc kind::f16 (fp16 in, fp32 acc), M=128, N=256:
//   dtype F32 (1<<4) | (N/8)<<17 | (M/16)<<24
#define MMA_IDESC 0x8400010u

#if defined(__CUDA_ARCH__) && defined(__CUDA_ARCH_FEAT_SM103_ALL)
#define HAS_TCGEN05 1
#else
#define HAS_TCGEN05 0
#endif

// elements per B chunk block: 256 x 64 fp16 = 16384 halves = 32KB
#define BCHUNK_ELEMS (HPAD * BK)

// ---------------------------------------------------------------------------
// Global scratch.
//  g_B   : per chunk, 32KB SW128 pre-swizzled fp16 Weff tile
//  g_Weff: fp32 Weff for the portable fallback path (never runs on GB300)
// ---------------------------------------------------------------------------
__device__ __align__(16) __half g_B[NCHUNK * BCHUNK_ELEMS];
__device__ __align__(16) float  g_Weff[HPAD * KPIX];

// ---------------------------------------------------------------------------
// Arch-neutral helpers
// ---------------------------------------------------------------------------
__device__ __forceinline__ uint32_t smem_to_u32(const void* p) {
    uint32_t a;
    asm("{ .reg .u64 t; cvta.to.shared.u64 t, %1; cvt.u32.u64 %0, t; }"
        : "=r"(a) : "l"(p));
    return a;
}
__device__ __forceinline__ unsigned long long pack2(float lo, float hi) {
    unsigned long long r;
    asm("mov.b64 %0, {%1, %2};" : "=l"(r) : "f"(lo), "f"(hi));
    return r;
}
__device__ __forceinline__ void fma2(unsigned long long& d,
                                     unsigned long long a,
                                     unsigned long long b) {
    asm("fma.rn.f32x2 %0, %1, %2, %0;" : "+l"(d) : "l"(a), "l"(b));
}
__device__ __forceinline__ float2 unpack2(unsigned long long v) {
    float2 f;
    asm("mov.b64 {%0, %1}, %2;" : "=f"(f.x), "=f"(f.y) : "l"(v));
    return f;
}
// packed rn convert: returns [fp16(hi_) | fp16(lo_)] (hi_ in upper 16 bits)
__device__ __forceinline__ uint32_t cvt2h(float hi_, float lo_) {
    uint32_t r;
    asm("cvt.rn.f16x2.f32 %0, %1, %2;" : "=r"(r) : "f"(hi_), "f"(lo_));
    return r;
}

// SW128 swizzle (bits [6:4] ^= bits [9:7])
__host__ __device__ __forceinline__ uint32_t sw128(uint32_t off) {
    return off ^ ((off >> 3) & 0x70);
}

#if HAS_TCGEN05
// ---------------------------------------------------------------------------
// tcgen05 / mbarrier / bulk-copy PTX helpers (sm_103a-only compilation)
// ---------------------------------------------------------------------------
__device__ __forceinline__ uint32_t elect_one_pred() {
    uint32_t pred;
    asm volatile(
        "{\n\t.reg .pred p;\n\t"
        "elect.sync _|p, 0xFFFFFFFF;\n\t"
        "selp.b32 %0, 1, 0, p;\n\t}"
        : "=r"(pred));
    return pred;
}

#define MBARRIER_INIT(addr, cnt) \
    asm volatile("mbarrier.init.shared.b64 [%0], %1;" \
        :: "r"((uint32_t)(addr)), "r"((uint32_t)(cnt)) : "memory")

#define MBARRIER_ARRIVE(addr) \
    asm volatile("mbarrier.arrive.release.cta.shared::cta.b64 _, [%0];" \
        :: "r"((uint32_t)(addr)) : "memory")

#define MBARRIER_EXPECT_TX(addr, bytes) \
    asm volatile("mbarrier.arrive.expect_tx.shared.b64 _, [%0], %1;" \
        :: "r"((uint32_t)(addr)), "r"((uint32_t)(bytes)) : "memory")

#define MBARRIER_WAIT_PARITY(addr, par) do { \
    uint32_t _m = (uint32_t)(addr); \
    uint32_t _p = (uint32_t)(par); \
    uint32_t _done; \
    asm volatile( \
        "{\n\t.reg .pred p;\n\t" \
        "mbarrier.try_wait.parity.acquire.cta.shared::cta.b64 p, [%1], %2;\n\t" \
        "selp.b32 %0, 1, 0, p;\n\t}" \
        : "=r"(_done) : "r"(_m), "r"(_p) : "memory"); \
    if (!_done) { \
        asm volatile( \
            "{\n\t.reg .pred P1;\n\t" \
            "WAIT_LOOP_%=:\n\t" \
            "mbarrier.try_wait.parity.acquire.cta.shared::cta.b64 P1, [%0], %1, 0x989680;\n\t" \
            "@P1 bra.uni WAIT_DONE_%=;\n\t" \
            "bra.uni WAIT_LOOP_%=;\n\t" \
            "WAIT_DONE_%=:\n\t}" \
            :: "r"(_m), "r"(_p) : "memory"); \
    } \
} while (0)

// plain bulk copy gmem -> smem, completion via tx mbarrier (UBLKCP)
#define CP_ASYNC_BULK_G2S(dst, src, bytes, mbar) \
    asm volatile( \
        "cp.async.bulk.shared::cluster.global.mbarrier::complete_tx::bytes " \
        "[%0], [%1], %2, [%3];" \
        :: "r"((uint32_t)(dst)), "l"(src), "r"((uint32_t)(bytes)), \
           "r"((uint32_t)(mbar)) : "memory")

#define TCGEN05_ALLOC(res_addr, ncols) \
    asm volatile("tcgen05.alloc.cta_group::1.sync.aligned.shared::cta.b32 [%0], %1;" \
        :: "r"((uint32_t)(res_addr)), "r"((uint32_t)(ncols)) : "memory")
#define TCGEN05_DEALLOC(tmem, ncols) \
    asm volatile("tcgen05.dealloc.cta_group::1.sync.aligned.b32 %0, %1;" \
        :: "r"(tmem), "r"((uint32_t)(ncols)))
#define TCGEN05_RELINQUISH() \
    asm volatile("tcgen05.relinquish_alloc_permit.cta_group::1.sync.aligned;")
#define TCGEN05_COMMIT(mbar) \
    asm volatile("tcgen05.commit.cta_group::1.mbarrier::arrive::one.shared::cluster.b64 [%0];" \
        :: "r"((uint32_t)(mbar)) : "memory")
#define TCGEN05_WAIT_LD() \
    asm volatile("tcgen05.wait::ld.sync.aligned;" ::: "memory")
#define TCGEN05_FENCE_BEFORE() \
    asm volatile("tcgen05.fence::before_thread_sync;" ::: "memory")
#define TCGEN05_FENCE_AFTER() \
    asm volatile("tcgen05.fence::after_thread_sync;" ::: "memory")
#define FENCE_PROXY_ASYNC() \
    asm volatile("fence.proxy.async.shared::cta;" ::: "memory")

#define TCGEN05_LD_32X32B_X32(r, tmem_addr) \
    asm volatile( \
        "tcgen05.ld.sync.aligned.32x32b.x32.b32 " \
        "{%0, %1, %2, %3, %4, %5, %6, %7, " \
        " %8, %9, %10, %11, %12, %13, %14, %15, " \
        " %16, %17, %18, %19, %20, %21, %22, %23, " \
        " %24, %25, %26, %27, %28, %29, %30, %31}, [%32];" \
        : "=r"((r)[0]),  "=r"((r)[1]),  "=r"((r)[2]),  "=r"((r)[3]), \
          "=r"((r)[4]),  "=r"((r)[5]),  "=r"((r)[6]),  "=r"((r)[7]), \
          "=r"((r)[8]),  "=r"((r)[9]),  "=r"((r)[10]), "=r"((r)[11]), \
          "=r"((r)[12]), "=r"((r)[13]), "=r"((r)[14]), "=r"((r)[15]), \
          "=r"((r)[16]), "=r"((r)[17]), "=r"((r)[18]), "=r"((r)[19]), \
          "=r"((r)[20]), "=r"((r)[21]), "=r"((r)[22]), "=r"((r)[23]), \
          "=r"((r)[24]), "=r"((r)[25]), "=r"((r)[26]), "=r"((r)[27]), \
          "=r"((r)[28]), "=r"((r)[29]), "=r"((r)[30]), "=r"((r)[31]) \
        : "r"(tmem_addr))

// SW128 K-major descriptor base (LBO=1, SBO=64, version=1, layout=SW128)
static constexpr uint64_t SMEM_DESC_BASE_SW128 =
    (uint64_t(2)  << 61) | (uint64_t(1) << 46) |
    (uint64_t(64) << 32) | (uint64_t(1) << 16);
#define MAKE_SMEM_DESC(addr) \
    (SMEM_DESC_BASE_SW128 | ((uint64_t)((addr) >> 4) & 0x3FFF))

__device__ __forceinline__ void mma_f16_ss(uint32_t d_tmem, uint64_t a_desc,
                                           uint64_t b_desc, uint32_t idesc,
                                           bool acc) {
    uint32_t en = acc ? 1u : 0u;
    asm volatile(
        "{\n\t.reg .pred p;\n\t"
        "setp.ne.u32 p, %5, 0;\n\t"
        "tcgen05.mma.cta_group::1.kind::f16 [%0], %1, %2, %3, "
        "{%4, %4, %4, %4}, p;\n\t}"
        :: "r"(d_tmem), "l"(a_desc), "l"(b_desc), "r"(idesc),
           "r"(0u), "r"(en)
        : "memory");
}
#endif // HAS_TCGEN05

// ---------------------------------------------------------------------------
// Kernel 1: fold conv into w0; write fp32 g_Weff (fallback) and SW128
// pre-swizzled fp16 chunk tiles g_B. grid=HPAD, block=832 (13*64).
// ---------------------------------------------------------------------------
__global__ void build_weff_kernel(const float* __restrict__ conv_w,
                                  const float* __restrict__ w0) {
    int j = blockIdx.x;      // hidden unit 0..255
    int p = threadIdx.x;     // k position 0..831
    float s = 0.0f;
    if (j < HID && p < KPIX) {
        int py = p / IMG, px = p % IMG;
        #pragma unroll
        for (int ky = 0; ky < 3; ky++)
            #pragma unroll
            for (int kx = 0; kx < 3; kx++) {
                int oy = py - ky, ox = px - kx;
                if (oy >= 0 && oy < OUT_HW && ox >= 0 && ox < OUT_HW)
                    s += conv_w[ky * 3 + kx] * w0[j * OPIX + oy * OUT_HW + ox];
            }
    }
    if (p < KPIX) g_Weff[j * KPIX + p] = s;

    int chunk = p >> 6, kin = p & 63;                // BK=64
    uint32_t off = (uint32_t)(j * 128 + kin * 2);    // bytes within 32KB tile
    uint32_t sw  = sw128(off);
    g_B[chunk * BCHUNK_ELEMS + (int)(sw >> 1)] = __float2half_rn(s);
}

// ---------------------------------------------------------------------------
// Kernel 2: fused  out = relu(X @ WeffT + b0) @ w1T + b1  (tcgen05 fp16).
// R16: TWO LOADER TEAMS on alternating chunks (structurally staggered
// pipelines inside one CTA) + dedicated B-copier warp + 4-deep ring.
//   warp 0    : MMA issuer
//   warp 1    : B bulk-copy issuer
//   warps 2-4 : team0 (even chunks -> stages 0,2)
//   warps 5-7 : team1 (odd  chunks -> stages 1,3)
// ---------------------------------------------------------------------------
// smem byte offsets
// ctrl: tmem ptr @0; bfull[4] @16..47; afull[4] @48..79; mdone[4] @80..111;
//       alldone @112
#define SM_CTRL   0
#define SM_A      1024       // 4 stages x 16KB = 65536
#define SM_B      66560      // 4 stages x 32KB = 131072
#define SM_W1P    197632     // 256*5*8 = 10240
#define SM_B0     207872     // 1024
#define SM_OUT    SM_A       // reused AFTER mainloop (A ring dead)
#define SMEM_TOTAL 208896    // 204KB, 1 CTA/SM

__global__ void __launch_bounds__(GEMM_THREADS, 1)
gemm_fused_kernel(const float* __restrict__ X,
                  const float* __restrict__ b0,
                  const float* __restrict__ w1,
                  const float* __restrict__ b1,
                  float* __restrict__ out) {
#if HAS_TCGEN05
    extern __shared__ char smem[];
    const uint32_t smem_base = smem_to_u32(smem);
    const int tid = threadIdx.x;
    const int wid = tid >> 5;
    const int lid = tid & 31;
    const int m0  = blockIdx.x * BM;

    const uint32_t mb_bfull   = smem_base + SM_CTRL + 16;  // +8*s
    const uint32_t mb_afull   = smem_base + SM_CTRL + 48;  // +8*s
    const uint32_t mb_mdone   = smem_base + SM_CTRL + 80;  // +8*s
    const uint32_t mb_alldone = smem_base + SM_CTRL + 112;

    // TMEM alloc (warp 0, collective): 256 fp32 accumulator columns
    if (wid == 0) TCGEN05_ALLOC(smem_base + SM_CTRL, 256);

    // epilogue weights into smem + mbarrier init
    if (tid < HPAD) {
        int j = tid;
        float* b0s = (float*)(smem + SM_B0);
        b0s[j] = (j < HID) ? b0[j] : 0.0f;
        unsigned long long* w1p = (unsigned long long*)(smem + SM_W1P);
        #pragma unroll
        for (int cc = 0; cc < 5; cc++) {
            float a  = (j < HID) ? w1[(2 * cc) * HID + j] : 0.0f;
            float bb = (j < HID) ? w1[(2 * cc + 1) * HID + j] : 0.0f;
            w1p[j * 5 + cc] = pack2(a, bb);
        }
    }
    if (tid == 0) {
        #pragma unroll
        for (int s = 0; s < NSTAGE; s++) {
            MBARRIER_INIT(mb_bfull + 8 * s, 1);
            MBARRIER_INIT(mb_afull + 8 * s, 3);   // 3 warps per team
            MBARRIER_INIT(mb_mdone + 8 * s, 1);
        }
        MBARRIER_INIT(mb_alldone, 1);
    }
    __syncthreads();

    uint32_t tmem;
    asm volatile("ld.shared.b32 %0, [%1];" : "=r"(tmem) : "r"(smem_base + SM_CTRL));

    if (wid == 0) {
        // =================== MMA issuer (warp 0) ===================
        for (int c = 0; c < NCHUNK; c++) {
            const int s  = c & 3;
            const int ph = (c >> 2) & 1;
            MBARRIER_WAIT_PARITY(mb_afull + 8 * s, ph);
            MBARRIER_WAIT_PARITY(mb_bfull + 8 * s, ph);
            if (elect_one_pred()) {
                TCGEN05_FENCE_AFTER();
                uint64_t ad = MAKE_SMEM_DESC(smem_base + SM_A + s * 16384);
                uint64_t bd = MAKE_SMEM_DESC(smem_base + SM_B + s * 32768);
                int nst = (c == NCHUNK - 1) ? 1 : 4;   // K=16 per MMA step
                for (int ks = 0; ks < nst; ks++) {
                    uint64_t o = (uint64_t)(ks * 2);   // +32B per 16 fp16
                    mma_f16_ss(tmem, ad + o, bd + o, MMA_IDESC, !(c == 0 && ks == 0));
                }
                TCGEN05_COMMIT(mb_mdone + 8 * s);
                if (c == NCHUNK - 1) TCGEN05_COMMIT(mb_alldone);
            }
        }
    } else if (wid == 1) {
        // =================== B copier (warp 1) ===================
        for (int c = 0; c < NCHUNK; c++) {
            const int s = c & 3;
            if (c >= NSTAGE) {
                const int ph = ((c >> 2) - 1) & 1;   // mdone from chunk c-4
                MBARRIER_WAIT_PARITY(mb_mdone + 8 * s, ph);
            }
            if (lid == 0) {
                MBARRIER_EXPECT_TX(mb_bfull + 8 * s, 32768);
                CP_ASYNC_BULK_G2S(smem_base + SM_B + s * 32768,
                                  (const void*)(g_B + c * BCHUNK_ELEMS),
                                  32768, mb_bfull + 8 * s);
            }
        }
    } else {
        // =================== loader teams (warps 2-7) ===================
        const int team = (wid >= 5) ? 1 : 0;
        const int ttid = tid - 64 - team * NTEAM;   // 0..95

        float4 v[2 * LPU];   // 22 float4 (88 regs)

        auto load_regs = [&](int c) {
            const int kvalid = KPIX - c * BK;      // 64 except last = 16
            #pragma unroll
            for (int i = 0; i < LPU; i++) {
                int u    = ttid + i * NTEAM;
                int row  = u >> 3;
                int ucol = u & 7;
                v[2 * i]     = make_float4(0.f, 0.f, 0.f, 0.f);
                v[2 * i + 1] = make_float4(0.f, 0.f, 0.f, 0.f);
                if (u < NUNIT && ucol * 8 < kvalid) {
                    const float* p = X + (long)(m0 + row) * KPIX + c * BK + ucol * 8;
                    v[2 * i]     = *(const float4*)p;
                    v[2 * i + 1] = *(const float4*)(p + 4);
                }
            }
        };
        auto store_stage = [&](int s) {
            char* ast = smem + SM_A + s * 16384;
            #pragma unroll
            for (int i = 0; i < LPU; i++) {
                int u    = ttid + i * NTEAM;
                int row  = u >> 3;
                int ucol = u & 7;
                if (u < NUNIT) {
                    uint32_t h01 = cvt2h(v[2*i].y,   v[2*i].x);
                    uint32_t h23 = cvt2h(v[2*i].w,   v[2*i].z);
                    uint32_t h45 = cvt2h(v[2*i+1].y, v[2*i+1].x);
                    uint32_t h67 = cvt2h(v[2*i+1].w, v[2*i+1].z);
                    uint32_t sw = sw128((uint32_t)(row * 128 + ucol * 16));
                    *(uint4*)(ast + sw) = make_uint4(h01, h23, h45, h67);
                }
            }
        };

        // team t handles chunks t, t+2, t+4, ... (stages alternate within
        // {t, t+2} of the 4-ring, disjoint between teams)
        for (int c = team; c < NCHUNK; c += 2) {
            const int s = c & 3;
            load_regs(c);                        // LDGs overlap the wait below
            if (c >= NSTAGE) {
                const int ph = ((c >> 2) - 1) & 1;
                MBARRIER_WAIT_PARITY(mb_mdone + 8 * s, ph);
            }
            store_stage(s);
            FENCE_PROXY_ASYNC();
            __syncwarp();
            if (lid == 0) MBARRIER_ARRIVE(mb_afull + 8 * s);
        }
    }

    // ---- all threads: wait for every MMA to complete ----
    MBARRIER_WAIT_PARITY(mb_alldone, 0);
    __syncthreads();
    TCGEN05_FENCE_AFTER();

    // ---- fused epilogue: h = relu(D + b0); out = h @ w1T + b1 ----
    const int sub  = wid & 3;          // TMEM subpartition (rows sub*32..+31)
    const int half = wid >> 2;         // 0: cols 0..127, 1: cols 128..255
    const int r    = sub * 32 + lid;
    const float* b0s = (const float*)(smem + SM_B0);
    const unsigned long long* w1p = (const unsigned long long*)(smem + SM_W1P);

    unsigned long long p2[5] = {0, 0, 0, 0, 0};
    #pragma unroll
    for (int blk = 0; blk < 4; blk++) {
        uint32_t d[32];
        TCGEN05_LD_32X32B_X32(d, tmem + half * 128 + blk * 32);
        TCGEN05_WAIT_LD();
        #pragma unroll
        for (int i = 0; i < 32; i++) {
            int j = half * 128 + blk * 32 + i;
            float h = fmaxf(__uint_as_float(d[i]) + b0s[j], 0.0f);
            unsigned long long hh = pack2(h, h);
            #pragma unroll
            for (int cc = 0; cc < 5; cc++) fma2(p2[cc], hh, w1p[j * 5 + cc]);
        }
    }
    TCGEN05_FENCE_BEFORE();

    // A ring is dead after the mainloop; reuse it as output staging.
    float* outst = (float*)(smem + SM_OUT);
    if (half == 0) {
        #pragma unroll
        for (int cc = 0; cc < 5; cc++) {
            float2 f = unpack2(p2[cc]);
            outst[r * 10 + 2 * cc]     = f.x;
            outst[r * 10 + 2 * cc + 1] = f.y;
        }
    }
    __syncthreads();
    if (half == 1) {
        long m = m0 + r;
        #pragma unroll
        for (int cc = 0; cc < 5; cc++) {
            float2 f = unpack2(p2[cc]);
            out[m * NOUT + 2 * cc]     = outst[r * 10 + 2 * cc]     + f.x + b1[2 * cc];
            out[m * NOUT + 2 * cc + 1] = outst[r * 10 + 2 * cc + 1] + f.y + b1[2 * cc + 1];
        }
    }
    __syncthreads();

    if (wid == 0) {
        TCGEN05_RELINQUISH();
        TCGEN05_DEALLOC(tmem, 256);
    }

#else  // ---------------- portable fallback (non-sm_103a passes) ------------
    extern __shared__ char smem[];
    const int tid  = threadIdx.x;
    const int r    = tid & 127;
    const int half = tid >> 7;
    const int m0   = blockIdx.x * BM;
    float* hbuf = (float*)smem;

    const float* xr = X + (long)(m0 + r) * KPIX;
    for (int j = half * 100; j < half * 100 + 100; j++) {
        const float* wr = g_Weff + j * KPIX;
        float s = 0.0f;
        for (int k = 0; k < KPIX; k += 4) {
            float4 xv = *(const float4*)(xr + k);
            float4 wv = *(const float4*)(wr + k);
            s += xv.x * wv.x + xv.y * wv.y + xv.z * wv.z + xv.w * wv.w;
        }
        hbuf[r * HID + j] = fmaxf(s + b0[j], 0.0f);
    }
    __syncthreads();
    if (half == 0) {
        float o[NOUT];
        #pragma unroll
        for (int c = 0; c < NOUT; c++) o[c] = b1[c];
        for (int j = 0; j < HID; j++) {
            float h = hbuf[r * HID + j];
            #pragma unroll
            for (int c = 0; c < NOUT; c++) o[c] += h * w1[c * HID + j];
        }
        #pragma unroll
        for (int c = 0; c < NOUT; c++) out[(long)(m0 + r) * NOUT + c] = o[c];
    }
#endif
}

// ---------------------------------------------------------------------------
// kernel_launch: graph-capturable, allocation-free.
// Inputs (metadata order): x, conv_w, w0, b0, w1, b1
// ---------------------------------------------------------------------------
extern "C" void kernel_launch(void* const* d_in, const int* in_sizes, int n_in,
                              void* d_out, int out_size) {
    const float* x      = (const float*)d_in[0];
    const float* conv_w = (const float*)d_in[1];
    const float* w0     = (const float*)d_in[2];
    const float* b0     = (const float*)d_in[3];
    const float* w1     = (const float*)d_in[4];
    const float* b1     = (const float*)d_in[5];
    float* out = (float*)d_out;

    cudaFuncSetAttribute(gemm_fused_kernel,
                         cudaFuncAttributeMaxDynamicSharedMemorySize, SMEM_TOTAL);

    build_weff_kernel<<<HPAD, NCHUNK * BK>>>(conv_w, w0);
    gemm_fused_kernel<<<BATCH / BM, GEMM_THREADS, SMEM_TOTAL>>>(x, b0, w1, b1, out);
}

// round 17
// speedup vs baseline: 1.3591x; 1.3591x over previous
#include <cuda_runtime.h>
#include <cuda.h>
#include <cstdint>

// ---------------------------------------------------------------------------
// Problem constants
// ---------------------------------------------------------------------------
#define BATCH   32768
#define IMG     28
#define KPIX    784      // GEMM K
#define OUT_HW  26
#define OPIX    676
#define HID     200
#define HPAD    256      // padded hidden (GEMM N)
#define NOUT    10

#define BM      256      // M rows per CTA = 2 tiles of 128 (dual TMEM accum)
#define BK      32       // K per chunk (fp32 -> 128B rows, SW128)
#define NCHUNK  25       // ceil(784/32); last chunk zero-filled by TMA OOB
#define NSTAGE  3        // ring depth
#define GEMM_THREADS 256

// idesc kind::tf32 (tf32 in, fp32 acc), M=128 (per tile), N=256:
//   dtype F32 (1<<4) | atype TF32 (2<<7) | btype TF32 (2<<10)
//   | (N/8)<<17 | (M/16)<<24
#define MMA_IDESC 0x8400910u

#if defined(__CUDA_ARCH__) && defined(__CUDA_ARCH_FEAT_SM103_ALL)
#define HAS_TCGEN05 1
#else
#define HAS_TCGEN05 0
#endif

// elements per B chunk block: 256 rows x 32 fp32 = 8192 floats = 32KB
#define BCHUNK_ELEMS (HPAD * BK)

// ---------------------------------------------------------------------------
// Global scratch.
//  g_B   : per chunk, 32KB SW128 pre-swizzled fp32 Weff tile (tf32 operand)
//  g_Weff: fp32 Weff for the portable fallback path (never runs on GB300)
// ---------------------------------------------------------------------------
__device__ __align__(16) float g_B[NCHUNK * BCHUNK_ELEMS];
__device__ __align__(16) float g_Weff[HPAD * KPIX];

// ---------------------------------------------------------------------------
// Arch-neutral helpers
// ---------------------------------------------------------------------------
__device__ __forceinline__ uint32_t smem_to_u32(const void* p) {
    uint32_t a;
    asm("{ .reg .u64 t; cvta.to.shared.u64 t, %1; cvt.u32.u64 %0, t; }"
        : "=r"(a) : "l"(p));
    return a;
}
__device__ __forceinline__ unsigned long long pack2(float lo, float hi) {
    unsigned long long r;
    asm("mov.b64 %0, {%1, %2};" : "=l"(r) : "f"(lo), "f"(hi));
    return r;
}
__device__ __forceinline__ void fma2(unsigned long long& d,
                                     unsigned long long a,
                                     unsigned long long b) {
    asm("fma.rn.f32x2 %0, %1, %2, %0;" : "+l"(d) : "l"(a), "l"(b));
}
__device__ __forceinline__ float2 unpack2(unsigned long long v) {
    float2 f;
    asm("mov.b64 {%0, %1}, %2;" : "=f"(f.x), "=f"(f.y) : "l"(v));
    return f;
}

// SW128 swizzle (bits [6:4] ^= bits [9:7])
__host__ __device__ __forceinline__ uint32_t sw128(uint32_t off) {
    return off ^ ((off >> 3) & 0x70);
}

#if HAS_TCGEN05
// ---------------------------------------------------------------------------
// tcgen05 / mbarrier / TMA PTX helpers (sm_103a-only compilation)
// ---------------------------------------------------------------------------
__device__ __forceinline__ uint32_t elect_one_pred() {
    uint32_t pred;
    asm volatile(
        "{\n\t.reg .pred p;\n\t"
        "elect.sync _|p, 0xFFFFFFFF;\n\t"
        "selp.b32 %0, 1, 0, p;\n\t}"
        : "=r"(pred));
    return pred;
}

#define MBARRIER_INIT(addr, cnt) \
    asm volatile("mbarrier.init.shared.b64 [%0], %1;" \
        :: "r"((uint32_t)(addr)), "r"((uint32_t)(cnt)) : "memory")

#define MBARRIER_EXPECT_TX(addr, bytes) \
    asm volatile("mbarrier.arrive.expect_tx.shared.b64 _, [%0], %1;" \
        :: "r"((uint32_t)(addr)), "r"((uint32_t)(bytes)) : "memory")

#define MBARRIER_WAIT_PARITY(addr, par) do { \
    uint32_t _m = (uint32_t)(addr); \
    uint32_t _p = (uint32_t)(par); \
    uint32_t _done; \
    asm volatile( \
        "{\n\t.reg .pred p;\n\t" \
        "mbarrier.try_wait.parity.acquire.cta.shared::cta.b64 p, [%1], %2;\n\t" \
        "selp.b32 %0, 1, 0, p;\n\t}" \
        : "=r"(_done) : "r"(_m), "r"(_p) : "memory"); \
    if (!_done) { \
        asm volatile( \
            "{\n\t.reg .pred P1;\n\t" \
            "WAIT_LOOP_%=:\n\t" \
            "mbarrier.try_wait.parity.acquire.cta.shared::cta.b64 P1, [%0], %1, 0x989680;\n\t" \
            "@P1 bra.uni WAIT_DONE_%=;\n\t" \
            "bra.uni WAIT_LOOP_%=;\n\t" \
            "WAIT_DONE_%=:\n\t}" \
            :: "r"(_m), "r"(_p) : "memory"); \
    } \
} while (0)

// plain bulk copy gmem -> smem, completion via tx mbarrier (UBLKCP)
#define CP_ASYNC_BULK_G2S(dst, src, bytes, mbar) \
    asm volatile( \
        "cp.async.bulk.shared::cluster.global.mbarrier::complete_tx::bytes " \
        "[%0], [%1], %2, [%3];" \
        :: "r"((uint32_t)(dst)), "l"(src), "r"((uint32_t)(bytes)), \
           "r"((uint32_t)(mbar)) : "memory")

// 2D TMA tensor load (HW-swizzled), completion via tx mbarrier (UTMALDG)
#define TMA_LOAD_2D(smem_addr, map_ptr, cx, cy, mbar) \
    asm volatile( \
        "cp.async.bulk.tensor.2d.shared::cta.global.tile.mbarrier::complete_tx::bytes " \
        "[%0], [%1, {%2, %3}], [%4];" \
        :: "r"((uint32_t)(smem_addr)), "l"(map_ptr), \
           "r"((int)(cx)), "r"((int)(cy)), "r"((uint32_t)(mbar)) : "memory")

#define TCGEN05_ALLOC(res_addr, ncols) \
    asm volatile("tcgen05.alloc.cta_group::1.sync.aligned.shared::cta.b32 [%0], %1;" \
        :: "r"((uint32_t)(res_addr)), "r"((uint32_t)(ncols)) : "memory")
#define TCGEN05_DEALLOC(tmem, ncols) \
    asm volatile("tcgen05.dealloc.cta_group::1.sync.aligned.b32 %0, %1;" \
        :: "r"(tmem), "r"((uint32_t)(ncols)))
#define TCGEN05_RELINQUISH() \
    asm volatile("tcgen05.relinquish_alloc_permit.cta_group::1.sync.aligned;")
#define TCGEN05_COMMIT(mbar) \
    asm volatile("tcgen05.commit.cta_group::1.mbarrier::arrive::one.shared::cluster.b64 [%0];" \
        :: "r"((uint32_t)(mbar)) : "memory")
#define TCGEN05_WAIT_LD() \
    asm volatile("tcgen05.wait::ld.sync.aligned;" ::: "memory")
#define TCGEN05_FENCE_BEFORE() \
    asm volatile("tcgen05.fence::before_thread_sync;" ::: "memory")
#define TCGEN05_FENCE_AFTER() \
    asm volatile("tcgen05.fence::after_thread_sync;" ::: "memory")

#define TCGEN05_LD_32X32B_X32(r, tmem_addr) \
    asm volatile( \
        "tcgen05.ld.sync.aligned.32x32b.x32.b32 " \
        "{%0, %1, %2, %3, %4, %5, %6, %7, " \
        " %8, %9, %10, %11, %12, %13, %14, %15, " \
        " %16, %17, %18, %19, %20, %21, %22, %23, " \
        " %24, %25, %26, %27, %28, %29, %30, %31}, [%32];" \
        : "=r"((r)[0]),  "=r"((r)[1]),  "=r"((r)[2]),  "=r"((r)[3]), \
          "=r"((r)[4]),  "=r"((r)[5]),  "=r"((r)[6]),  "=r"((r)[7]), \
          "=r"((r)[8]),  "=r"((r)[9]),  "=r"((r)[10]), "=r"((r)[11]), \
          "=r"((r)[12]), "=r"((r)[13]), "=r"((r)[14]), "=r"((r)[15]), \
          "=r"((r)[16]), "=r"((r)[17]), "=r"((r)[18]), "=r"((r)[19]), \
          "=r"((r)[20]), "=r"((r)[21]), "=r"((r)[22]), "=r"((r)[23]), \
          "=r"((r)[24]), "=r"((r)[25]), "=r"((r)[26]), "=r"((r)[27]), \
          "=r"((r)[28]), "=r"((r)[29]), "=r"((r)[30]), "=r"((r)[31]) \
        : "r"(tmem_addr))

// SW128 K-major descriptor base (LBO=1, SBO=64, version=1, layout=SW128)
static constexpr uint64_t SMEM_DESC_BASE_SW128 =
    (uint64_t(2)  << 61) | (uint64_t(1) << 46) |
    (uint64_t(64) << 32) | (uint64_t(1) << 16);
#define MAKE_SMEM_DESC(addr) \
    (SMEM_DESC_BASE_SW128 | ((uint64_t)((addr) >> 4) & 0x3FFF))

__device__ __forceinline__ void mma_tf32_ss(uint32_t d_tmem, uint64_t a_desc,
                                            uint64_t b_desc, uint32_t idesc,
                                            bool acc) {
    uint32_t en = acc ? 1u : 0u;
    asm volatile(
        "{\n\t.reg .pred p;\n\t"
        "setp.ne.u32 p, %5, 0;\n\t"
        "tcgen05.mma.cta_group::1.kind::tf32 [%0], %1, %2, %3, "
        "{%4, %4, %4, %4}, p;\n\t}"
        :: "r"(d_tmem), "l"(a_desc), "l"(b_desc), "r"(idesc),
           "r"(0u), "r"(en)
        : "memory");
}
#endif // HAS_TCGEN05

// ---------------------------------------------------------------------------
// Kernel 1: fold conv into w0; write fp32 g_Weff (fallback) and SW128
// pre-swizzled fp32 chunk tiles g_B. grid=HPAD, block=800 (25*32).
// ---------------------------------------------------------------------------
__global__ void build_weff_kernel(const float* __restrict__ conv_w,
                                  const float* __restrict__ w0) {
    int j = blockIdx.x;      // hidden unit 0..255
    int p = threadIdx.x;     // k position 0..799
    float s = 0.0f;
    if (j < HID && p < KPIX) {
        int py = p / IMG, px = p % IMG;
        #pragma unroll
        for (int ky = 0; ky < 3; ky++)
            #pragma unroll
            for (int kx = 0; kx < 3; kx++) {
                int oy = py - ky, ox = px - kx;
                if (oy >= 0 && oy < OUT_HW && ox >= 0 && ox < OUT_HW)
                    s += conv_w[ky * 3 + kx] * w0[j * OPIX + oy * OUT_HW + ox];
            }
    }
    if (p < KPIX) g_Weff[j * KPIX + p] = s;

    int chunk = p >> 5, kin = p & 31;                // BK=32
    uint32_t off = (uint32_t)(j * 128 + kin * 4);    // bytes within 32KB tile
    uint32_t sw  = sw128(off);
    g_B[chunk * BCHUNK_ELEMS + (int)(sw >> 2)] = s;
}

// ---------------------------------------------------------------------------
// Kernel 2: fused  out = relu(X @ WeffT + b0) @ w1T + b1  (tcgen05 tf32).
// NO SIMT LOADER: A arrives via 2D TMA tensor loads (HW SW128 swizzle, OOB
// zero-fill covers the K-tail), B via one bulk copy per chunk. BM=256 as two
// M=128 tiles (dual TMEM accumulators), grid=128 = single wave.
//   warp 0 : MMA issuer     warp 1 : copy issuer     warps 2-7 : epilogue only
// ---------------------------------------------------------------------------
// smem: ctrl @0 (tmem ptr @0; full[3] @16..39; mdone[3] @48..71; alldone @80)
#define SM_CTRL   0
#define SM_A      1024       // 3 stages x 32KB (t0 16KB | t1 16KB) = 98304
#define SM_B      99328      // 3 stages x 32KB = 98304
#define SM_W1P    197632     // 256*5*8 = 10240
#define SM_B0     207872     // 1024
#define SM_OUT    SM_A       // reused AFTER mainloop (A ring dead)
#define SMEM_TOTAL 208896    // 204KB, 1 CTA/SM

__global__ void __launch_bounds__(GEMM_THREADS, 1)
gemm_fused_kernel(const __grid_constant__ CUtensorMap tmX,
                  const float* __restrict__ X,
                  const float* __restrict__ b0,
                  const float* __restrict__ w1,
                  const float* __restrict__ b1,
                  float* __restrict__ out) {
#if HAS_TCGEN05
    extern __shared__ char smem[];
    const uint32_t smem_base = smem_to_u32(smem);
    const int tid = threadIdx.x;
    const int wid = tid >> 5;
    const int lid = tid & 31;
    const int m0  = blockIdx.x * BM;

    const uint32_t mb_full    = smem_base + SM_CTRL + 16;  // +8*s
    const uint32_t mb_mdone   = smem_base + SM_CTRL + 48;  // +8*s
    const uint32_t mb_alldone = smem_base + SM_CTRL + 80;

    // TMEM alloc (warp 0, collective): all 512 columns (two 256-col tiles)
    if (wid == 0) TCGEN05_ALLOC(smem_base + SM_CTRL, 512);

    // epilogue weights into smem + mbarrier init
    if (tid < HPAD) {
        int j = tid;
        float* b0s = (float*)(smem + SM_B0);
        b0s[j] = (j < HID) ? b0[j] : 0.0f;
        unsigned long long* w1p = (unsigned long long*)(smem + SM_W1P);
        #pragma unroll
        for (int cc = 0; cc < 5; cc++) {
            float a  = (j < HID) ? w1[(2 * cc) * HID + j] : 0.0f;
            float bb = (j < HID) ? w1[(2 * cc + 1) * HID + j] : 0.0f;
            w1p[j * 5 + cc] = pack2(a, bb);
        }
    }
    if (tid == 0) {
        #pragma unroll
        for (int s = 0; s < NSTAGE; s++) {
            MBARRIER_INIT(mb_full  + 8 * s, 1);
            MBARRIER_INIT(mb_mdone + 8 * s, 1);
        }
        MBARRIER_INIT(mb_alldone, 1);
    }
    __syncthreads();

    uint32_t tmem;
    asm volatile("ld.shared.b32 %0, [%1];" : "=r"(tmem) : "r"(smem_base + SM_CTRL));

    if (wid == 0) {
        // =================== MMA issuer (warp 0) ===================
        for (int c = 0; c < NCHUNK; c++) {
            const int s  = c % NSTAGE;
            const int ph = (c / NSTAGE) & 1;
            MBARRIER_WAIT_PARITY(mb_full + 8 * s, ph);
            if (elect_one_pred()) {
                TCGEN05_FENCE_AFTER();
                uint64_t a0 = MAKE_SMEM_DESC(smem_base + SM_A + s * 32768);
                uint64_t a1 = MAKE_SMEM_DESC(smem_base + SM_A + s * 32768 + 16384);
                uint64_t bd = MAKE_SMEM_DESC(smem_base + SM_B + s * 32768);
                #pragma unroll
                for (int ks = 0; ks < 4; ks++) {      // K=8 per tf32 MMA step
                    uint64_t o = (uint64_t)(ks * 2);   // +32B per 8 fp32
                    bool acc = !(c == 0 && ks == 0);
                    mma_tf32_ss(tmem,       a0 + o, bd + o, MMA_IDESC, acc);
                    mma_tf32_ss(tmem + 256, a1 + o, bd + o, MMA_IDESC, acc);
                }
                TCGEN05_COMMIT(mb_mdone + 8 * s);
                if (c == NCHUNK - 1) TCGEN05_COMMIT(mb_alldone);
            }
        }
    } else if (wid == 1) {
        // =================== copy issuer (warp 1) ===================
        for (int c = 0; c < NCHUNK; c++) {
            const int s = c % NSTAGE;
            if (c >= NSTAGE) {
                const int ph = (c / NSTAGE - 1) & 1;   // mdone from chunk c-3
                MBARRIER_WAIT_PARITY(mb_mdone + 8 * s, ph);
            }
            if (lid == 0) {
                const uint32_t full = mb_full + 8 * s;
                MBARRIER_EXPECT_TX(full, 65536);   // A 2x16KB + B 32KB
                TMA_LOAD_2D(smem_base + SM_A + s * 32768,
                            &tmX, c * BK, m0,       full);
                TMA_LOAD_2D(smem_base + SM_A + s * 32768 + 16384,
                            &tmX, c * BK, m0 + 128, full);
                CP_ASYNC_BULK_G2S(smem_base + SM_B + s * 32768,
                                  (const void*)(g_B + c * BCHUNK_ELEMS),
                                  32768, full);
            }
        }
    }
    // warps 2-7: straight to the epilogue wait.

    // ---- all threads: wait for every MMA to complete ----
    MBARRIER_WAIT_PARITY(mb_alldone, 0);
    __syncthreads();
    TCGEN05_FENCE_AFTER();

    // ---- fused epilogue: h = relu(D + b0); out = h @ w1T + b1 (both tiles)
    const int sub  = wid & 3;          // TMEM subpartition (rows sub*32..+31)
    const int half = wid >> 2;         // 0: cols 0..127, 1: cols 128..255
    const int r    = sub * 32 + lid;
    const float* b0s = (const float*)(smem + SM_B0);
    const unsigned long long* w1p = (const unsigned long long*)(smem + SM_W1P);
    float* outst = (float*)(smem + SM_OUT);   // A ring dead; 256 rows x 10

    #pragma unroll
    for (int t = 0; t < 2; t++) {
        unsigned long long p2[5] = {0, 0, 0, 0, 0};
        #pragma unroll
        for (int blk = 0; blk < 4; blk++) {
            uint32_t d[32];
            TCGEN05_LD_32X32B_X32(d, tmem + t * 256 + half * 128 + blk * 32);
            TCGEN05_WAIT_LD();
            #pragma unroll
            for (int i = 0; i < 32; i++) {
                int j = half * 128 + blk * 32 + i;
                float h = fmaxf(__uint_as_float(d[i]) + b0s[j], 0.0f);
                unsigned long long hh = pack2(h, h);
                #pragma unroll
                for (int cc = 0; cc < 5; cc++) fma2(p2[cc], hh, w1p[j * 5 + cc]);
            }
        }
        TCGEN05_FENCE_BEFORE();

        int rg = t * 128 + r;
        if (half == 0) {
            #pragma unroll
            for (int cc = 0; cc < 5; cc++) {
                float2 f = unpack2(p2[cc]);
                outst[rg * 10 + 2 * cc]     = f.x;
                outst[rg * 10 + 2 * cc + 1] = f.y;
            }
        }
        __syncthreads();
        if (half == 1) {
            long m = m0 + rg;
            #pragma unroll
            for (int cc = 0; cc < 5; cc++) {
                float2 f = unpack2(p2[cc]);
                out[m * NOUT + 2 * cc]     = outst[rg * 10 + 2 * cc]     + f.x + b1[2 * cc];
                out[m * NOUT + 2 * cc + 1] = outst[rg * 10 + 2 * cc + 1] + f.y + b1[2 * cc + 1];
            }
        }
        __syncthreads();
    }

    if (wid == 0) {
        TCGEN05_RELINQUISH();
        TCGEN05_DEALLOC(tmem, 512);
    }

#else  // ---------------- portable fallback (non-sm_103a passes) ------------
    extern __shared__ char smem[];
    const int tid = threadIdx.x;
    const int m0  = blockIdx.x * BM;
    const float* xr = X + (long)(m0 + tid) * KPIX;
    float o[NOUT];
    #pragma unroll
    for (int c = 0; c < NOUT; c++) o[c] = b1[c];
    for (int j = 0; j < HID; j++) {
        const float* wr = g_Weff + j * KPIX;
        float s = 0.0f;
        for (int k = 0; k < KPIX; k += 4) {
            float4 xv = *(const float4*)(xr + k);
            float4 wv = *(const float4*)(wr + k);
            s += xv.x * wv.x + xv.y * wv.y + xv.z * wv.z + xv.w * wv.w;
        }
        float h = fmaxf(s + b0[j], 0.0f);
        #pragma unroll
        for (int c = 0; c < NOUT; c++) o[c] += h * w1[c * HID + j];
    }
    #pragma unroll
    for (int c = 0; c < NOUT; c++) out[(long)(m0 + tid) * NOUT + c] = o[c];
#endif
}

// ---------------------------------------------------------------------------
// kernel_launch: graph-capturable, allocation-free.
// Tensor map is built host-side via the driver entry point fetched through
// cudart (no -lcuda linkage). Inputs: x, conv_w, w0, b0, w1, b1
// ---------------------------------------------------------------------------
typedef CUresult (*PFN_encodeTiled)(
    CUtensorMap*, CUtensorMapDataType, cuuint32_t, void*,
    const cuuint64_t*, const cuuint64_t*, const cuuint32_t*, const cuuint32_t*,
    CUtensorMapInterleave, CUtensorMapSwizzle, CUtensorMapL2promotion,
    CUtensorMapFloatOOBfill);

extern "C" void kernel_launch(void* const* d_in, const int* in_sizes, int n_in,
                              void* d_out, int out_size) {
    const float* x      = (const float*)d_in[0];
    const float* conv_w = (const float*)d_in[1];
    const float* w0     = (const float*)d_in[2];
    const float* b0     = (const float*)d_in[3];
    const float* w1     = (const float*)d_in[4];
    const float* b1     = (const float*)d_in[5];
    float* out = (float*)d_out;

    // --- build the X tensor map (pure host work; capture-safe) ---
    void* fn = nullptr;
    cudaDriverEntryPointQueryResult qr;
#if CUDART_VERSION >= 12050
    cudaGetDriverEntryPointByVersion("cuTensorMapEncodeTiled", &fn, 12000,
                                     cudaEnableDefault, &qr);
#else
    cudaGetDriverEntryPoint("cuTensorMapEncodeTiled", &fn,
                            cudaEnableDefault, &qr);
#endif
    CUtensorMap tmX;
    {
        PFN_encodeTiled enc = (PFN_encodeTiled)fn;
        cuuint64_t dims[2]    = {(cuuint64_t)KPIX, (cuuint64_t)BATCH};
        cuuint64_t strides[1] = {(cuuint64_t)KPIX * sizeof(float)};
        cuuint32_t box[2]     = {(cuuint32_t)BK, 128};   // 128B x 128 rows
        cuuint32_t estr[2]    = {1, 1};
        enc(&tmX, CU_TENSOR_MAP_DATA_TYPE_FLOAT32, 2, (void*)x,
            dims, strides, box, estr,
            CU_TENSOR_MAP_INTERLEAVE_NONE, CU_TENSOR_MAP_SWIZZLE_128B,
            CU_TENSOR_MAP_L2_PROMOTION_L2_128B,
            CU_TENSOR_MAP_FLOAT_OOB_FILL_NONE);
    }

    cudaFuncSetAttribute(gemm_fused_kernel,
                         cudaFuncAttributeMaxDynamicSharedMemorySize, SMEM_TOTAL);

    build_weff_kernel<<<HPAD, NCHUNK * BK>>>(conv_w, w0);
    gemm_fused_kernel<<<BATCH / BM, GEMM_THREADS, SMEM_TOTAL>>>(
        tmX, x, b0, w1, b1, out);
}